// round 5
// baseline (speedup 1.0000x reference)
#include <cuda_runtime.h>

typedef unsigned long long u64;

// ---------------- f32x2 packed-math helpers (sm_103a) ----------------
__device__ __forceinline__ u64 f2fma(u64 a, u64 b, u64 c) {
    u64 d;
    asm("fma.rn.f32x2 %0, %1, %2, %3;" : "=l"(d) : "l"(a), "l"(b), "l"(c));
    return d;
}
__device__ __forceinline__ u64 f2mul(u64 a, u64 b) {
    u64 d;
    asm("mul.rn.f32x2 %0, %1, %2;" : "=l"(d) : "l"(a), "l"(b));
    return d;
}
__device__ __forceinline__ u64 fpack(float x, float y) {
    u64 d;
    asm("mov.b64 %0, {%1, %2};" : "=l"(d) : "f"(x), "f"(y));
    return d;
}
__device__ __forceinline__ float2 funpack(u64 a) {
    float2 r;
    asm("mov.b64 {%0, %1}, %2;" : "=f"(r.x), "=f"(r.y) : "l"(a));
    return r;
}

// ---------------- problem constants ----------------
#define NN     50000
#define KC     128
#define PC     256
#define BN     8
#define NT     512
#define NI     4
#define EPSV   1e-6f

// smem layout (float offsets)
#define OFF_RES 0          // [8][9][128]            9216
#define OFF_H2  9216       // [8][9][128] x float2   18432
#define OFF_HC  27648      // [8][9][256]            18432
#define OFF_U   46080      // [45][20] (dup pairs)   900
#define OFF_G   46980      // [4][3][128]            1536
#define SMEM_FLOATS 48516

// ---------------- linear_in: h[9][K] @ Win[K][2K] -> hc[9][2K] ----------------
// NT=512: thread = (p-pair t in 0..127) x (node group of 2). 18 u64 accs.
// h LDS.128 is warp-broadcast; W LDG coalesced over t.
template<int ML, int M0>
__device__ __forceinline__ void lin_in(const float* __restrict__ W,
                                       const float* __restrict__ s_h2,
                                       float* __restrict__ s_hc,
                                       int t, int b0)
{
    u64 acc[2][ML];
    #pragma unroll
    for (int b = 0; b < 2; b++)
        #pragma unroll
        for (int m = 0; m < ML; m++) acc[b][m] = 0ull;

    const float* wcol = W + 2 * t;
    #pragma unroll 4
    for (int k = 0; k < KC; k += 2) {
        u64 w0 = *(const u64*)(wcol + (size_t)k * PC);
        u64 w1 = *(const u64*)(wcol + (size_t)(k + 1) * PC);
        #pragma unroll
        for (int b = 0; b < 2; b++) {
            #pragma unroll
            for (int m = 0; m < ML; m++) {
                const ulonglong2 h = *(const ulonglong2*)
                    (s_h2 + (((b0 + b) * 9 + M0 + m) * 128 + k) * 2);
                acc[b][m] = f2fma(h.x, w0, acc[b][m]);
                acc[b][m] = f2fma(h.y, w1, acc[b][m]);
            }
        }
    }
    #pragma unroll
    for (int b = 0; b < 2; b++)
        #pragma unroll
        for (int m = 0; m < ML; m++)
            *(u64*)(s_hc + ((b0 + b) * 9 + M0 + m) * 256 + 2 * t) = acc[b][m];
}

// ---------------- linear_out: tp[9][2K] @ Wout[2K][K] + skip ----------------
// NT=512: thread = (col-pair cp in 0..63) x (node bg in 0..7). 9 u64 accs.
template<int ML, int M0>
__device__ __forceinline__ void lin_out(const float* __restrict__ W,
                                        const float* __restrict__ s_hc,
                                        float* __restrict__ s_res,
                                        int cp, int bg)
{
    u64 acc[ML];
    #pragma unroll
    for (int m = 0; m < ML; m++) acc[m] = 0ull;

    const float* wcol = W + 2 * cp;
    #pragma unroll 2
    for (int p = 0; p < PC; p += 4) {
        u64 w0 = *(const u64*)(wcol + (size_t)(p + 0) * KC);
        u64 w1 = *(const u64*)(wcol + (size_t)(p + 1) * KC);
        u64 w2 = *(const u64*)(wcol + (size_t)(p + 2) * KC);
        u64 w3 = *(const u64*)(wcol + (size_t)(p + 3) * KC);
        #pragma unroll
        for (int m = 0; m < ML; m++) {
            const float4 hv = *(const float4*)
                (s_hc + (bg * 9 + M0 + m) * 256 + p);
            acc[m] = f2fma(fpack(hv.x, hv.x), w0, acc[m]);
            acc[m] = f2fma(fpack(hv.y, hv.y), w1, acc[m]);
            acc[m] = f2fma(fpack(hv.z, hv.z), w2, acc[m]);
            acc[m] = f2fma(fpack(hv.w, hv.w), w3, acc[m]);
        }
    }
    #pragma unroll
    for (int m = 0; m < ML; m++) {
        float* rr = s_res + (bg * 9 + M0 + m) * 128 + 2 * cp;
        float2 r = *(float2*)rr;
        float2 a = funpack(acc[m]);
        r.x += a.x; r.y += a.y;
        *(float2*)rr = r;
    }
}

// ---------------- fused 4-iteration kernel, 8 nodes per CTA, 512 threads ----------------
__global__ void __launch_bounds__(NT, 1)
cg_kernel(const float* __restrict__ f0, const float* __restrict__ f1,
          const float* __restrict__ f2, const float* __restrict__ U,
          const float* __restrict__ gamma, const float* __restrict__ Win,
          const float* __restrict__ Wout, float* __restrict__ out)
{
    extern __shared__ float sm[];
    float* s_res = sm + OFF_RES;
    float* s_h2  = sm + OFF_H2;
    float* s_hc  = sm + OFF_HC;
    float* s_U   = sm + OFF_U;
    float* s_g   = sm + OFF_G;

    const int tid = threadIdx.x;
    const int n0  = blockIdx.x * BN;

    // --- load features: s_res[b][m][k], m packed [f0 | f1(3) | f2(5)] ---
    {
        float4* dst = (float4*)s_res;
        for (int idx = tid; idx < BN * 9 * 32; idx += NT) {
            int b   = idx / 288;
            int rem = idx - b * 288;
            int m   = rem >> 5;
            int q   = rem & 31;
            int n   = n0 + b;
            const float* src;
            if (m == 0)      src = f0 + (size_t)n * 128;
            else if (m < 4)  src = f1 + (size_t)n * 384 + (m - 1) * 128;
            else             src = f2 + (size_t)n * 640 + (m - 4) * 128;
            dst[idx] = ((const float4*)src)[q];
        }
    }
    // --- symmetrize U into duplicated pair layout ---
    for (int tt = tid; tt < 45 * 9; tt += NT) {
        int pair = tt / 9, c = tt - pair * 9;
        int a = 0, rem = pair;
        while (rem > 8 - a) { rem -= 9 - a; a++; }
        int bb = a + rem;
        float u = U[(a * 9 + bb) * 9 + c];
        if (a != bb) u += U[(bb * 9 + a) * 9 + c];
        s_U[pair * 20 + 2 * c]     = u;
        s_U[pair * 20 + 2 * c + 1] = u;
    }
    for (int tt = tid; tt < NI * 3 * KC; tt += NT) s_g[tt] = gamma[tt];
    __syncthreads();

    #pragma unroll 1
    for (int it = 0; it < NI; it++) {
        // ---------- EquivariantRMSNorm -> duplicated h {h,h} ----------
        for (int idx = tid; idx < BN * KC; idx += NT) {
            int b = idx >> 7, k = idx & 127;
            const float* r = s_res + b * 1152 + k;
            float x0 = r[0];
            float x1 = r[128], x2 = r[256],  x3 = r[384];
            float x4 = r[512], x5 = r[640],  x6 = r[768], x7 = r[896], x8 = r[1024];
            float i0 = rsqrtf(x0 * x0 + EPSV);
            float i1 = rsqrtf((x1*x1 + x2*x2 + x3*x3) * (1.0f/3.0f) + EPSV);
            float i2 = rsqrtf((x4*x4 + x5*x5 + x6*x6 + x7*x7 + x8*x8) * 0.2f + EPSV);
            float g0 = s_g[(it * 3 + 0) * 128 + k];
            float g1 = s_g[(it * 3 + 1) * 128 + k];
            float g2 = s_g[(it * 3 + 2) * 128 + k];
            float2* h = ((float2*)s_h2) + b * 1152 + k;
            float v;
            v = x0 * i0 * g0; h[0]    = make_float2(v, v);
            v = x1 * i1 * g1; h[128]  = make_float2(v, v);
            v = x2 * i1 * g1; h[256]  = make_float2(v, v);
            v = x3 * i1 * g1; h[384]  = make_float2(v, v);
            v = x4 * i2 * g2; h[512]  = make_float2(v, v);
            v = x5 * i2 * g2; h[640]  = make_float2(v, v);
            v = x6 * i2 * g2; h[768]  = make_float2(v, v);
            v = x7 * i2 * g2; h[896]  = make_float2(v, v);
            v = x8 * i2 * g2; h[1024] = make_float2(v, v);
        }
        __syncthreads();

        // ---------- linear_in (K -> 2K) ----------
        {
            const int t  = tid & 127;
            const int b0 = (tid >> 7) * 2;
            const float* Wi = Win + (size_t)(it * 3) * KC * PC;
            lin_in<1, 0>(Wi + 0 * KC * PC, s_h2, s_hc, t, b0);
            lin_in<3, 1>(Wi + 1 * KC * PC, s_h2, s_hc, t, b0);
            lin_in<5, 4>(Wi + 2 * KC * PC, s_h2, s_hc, t, b0);
        }
        __syncthreads();

        // ---------- CG tensor product, in-place on s_hc, single pass ----------
        {
            const int p2 = tid & 127;
            const int bq = (tid >> 7) * 2;
            float* base0 = s_hc + bq * 2304 + 2 * p2;
            float* base1 = base0 + 2304;
            u64 acc0[9], acc1[9];
            #pragma unroll
            for (int c = 0; c < 9; c++) { acc0[c] = 0ull; acc1[c] = 0ull; }
            int pair = 0;
            for (int a = 0; a < 9; a++) {
                u64 va0 = *(const u64*)(base0 + a * 256);
                u64 va1 = *(const u64*)(base1 + a * 256);
                for (int bb = a; bb < 9; bb++) {
                    u64 vb0 = *(const u64*)(base0 + bb * 256);
                    u64 vb1 = *(const u64*)(base1 + bb * 256);
                    u64 pr0 = f2mul(va0, vb0);
                    u64 pr1 = f2mul(va1, vb1);
                    const u64* u = (const u64*)(s_U + pair * 20);
                    #pragma unroll
                    for (int c = 0; c < 9; c++) {
                        u64 uc = u[c];
                        acc0[c] = f2fma(pr0, uc, acc0[c]);
                        acc1[c] = f2fma(pr1, uc, acc1[c]);
                    }
                    pair++;
                }
            }
            #pragma unroll
            for (int c = 0; c < 9; c++) {
                *(u64*)(base0 + c * 256) = acc0[c];
                *(u64*)(base1 + c * 256) = acc1[c];
            }
        }
        __syncthreads();

        // ---------- linear_out (2K -> K) + skip ----------
        {
            const int cp = tid & 63;
            const int bg = tid >> 6;
            const float* Wo = Wout + (size_t)(it * 3) * PC * KC;
            lin_out<1, 0>(Wo + 0 * PC * KC, s_hc, s_res, cp, bg);
            lin_out<3, 1>(Wo + 1 * PC * KC, s_hc, s_res, cp, bg);
            lin_out<5, 4>(Wo + 2 * PC * KC, s_hc, s_res, cp, bg);
        }
        __syncthreads();
    }

    // --- write out [N][9][128] ---
    {
        float4* o = (float4*)(out + (size_t)n0 * 1152);
        const float4* s = (const float4*)s_res;
        for (int idx = tid; idx < BN * 9 * 32; idx += NT) o[idx] = s[idx];
    }
}

extern "C" void kernel_launch(void* const* d_in, const int* in_sizes, int n_in,
                              void* d_out, int out_size)
{
    const float* f0 = (const float*)d_in[0];
    const float* f1 = (const float*)d_in[1];
    const float* f2 = (const float*)d_in[2];
    const float* U  = (const float*)d_in[3];
    const float* g  = (const float*)d_in[4];
    const float* Wi = (const float*)d_in[5];
    const float* Wo = (const float*)d_in[6];
    float* out = (float*)d_out;

    const int smem_bytes = SMEM_FLOATS * (int)sizeof(float);
    cudaFuncSetAttribute(cg_kernel, cudaFuncAttributeMaxDynamicSharedMemorySize, smem_bytes);
    cg_kernel<<<NN / BN, NT, smem_bytes>>>(f0, f1, f2, U, g, Wi, Wo, out);
}

// round 6
// speedup vs baseline: 1.1141x; 1.1141x over previous
#include <cuda_runtime.h>

typedef unsigned long long u64;

// ---------------- f32x2 packed-math helpers (sm_103a) ----------------
__device__ __forceinline__ u64 f2fma(u64 a, u64 b, u64 c) {
    u64 d;
    asm("fma.rn.f32x2 %0, %1, %2, %3;" : "=l"(d) : "l"(a), "l"(b), "l"(c));
    return d;
}
__device__ __forceinline__ u64 f2mul(u64 a, u64 b) {
    u64 d;
    asm("mul.rn.f32x2 %0, %1, %2;" : "=l"(d) : "l"(a), "l"(b));
    return d;
}
__device__ __forceinline__ u64 fpack(float x, float y) {
    u64 d;
    asm("mov.b64 %0, {%1, %2};" : "=l"(d) : "f"(x), "f"(y));
    return d;
}
__device__ __forceinline__ float2 funpack(u64 a) {
    float2 r;
    asm("mov.b64 {%0, %1}, %2;" : "=f"(r.x), "=f"(r.y) : "l"(a));
    return r;
}

// ---------------- problem constants ----------------
#define NN     50000
#define KC     128
#define PC     256
#define BN     8
#define NT     512
#define NI     4
#define EPSV   1e-6f

// smem layout (float offsets)
#define OFF_RES 0          // [8][9][128]  residual        9216
#define OFF_H   9216       // [8][9][128]  normed h        9216
#define OFF_HC  18432      // [8][9][256]  hc / tp         18432
#define OFF_U   36864      // [45][9] scalar sym U         405
#define OFF_G   37312      // [4][3][128]  gamma           1536
#define SMEM_FLOATS 38848

// ---------------- linear_in: h[9][K] @ Win[K][2K] -> hc[9][2K] ----------------
// f32x2 accumulators over k-parity (horizontal add at end).
// Thread owns 2 p-cols (p0, p0+128) x 2 nodes x ML m-rows.
// h read as natural float4 (ulonglong2: halves are adjacent-k pairs) -> no dup.
// Weight k-pairs {W[k][p],W[k+1][p]} built with 2 LDG.32 + fpack, amortized 18x.
template<int ML, int M0>
__device__ __forceinline__ void lin_in(const float* __restrict__ W,
                                       const float* __restrict__ s_h,
                                       float* __restrict__ s_hc,
                                       int p0, int ng)
{
    u64 acc[2][2][ML];   // [pc][b][m]
    #pragma unroll
    for (int pc = 0; pc < 2; pc++)
        #pragma unroll
        for (int b = 0; b < 2; b++)
            #pragma unroll
            for (int m = 0; m < ML; m++) acc[pc][b][m] = 0ull;

    const float* w0 = W + p0;
    const float* w1 = W + p0 + 128;

    #pragma unroll 4
    for (int k = 0; k < KC; k += 4) {
        const float* wk0 = w0 + (size_t)k * PC;
        const float* wk1 = w1 + (size_t)k * PC;
        u64 wp00 = fpack(wk0[0],      wk0[PC]);
        u64 wp01 = fpack(wk0[2 * PC], wk0[3 * PC]);
        u64 wp10 = fpack(wk1[0],      wk1[PC]);
        u64 wp11 = fpack(wk1[2 * PC], wk1[3 * PC]);
        #pragma unroll
        for (int b = 0; b < 2; b++) {
            #pragma unroll
            for (int m = 0; m < ML; m++) {
                const ulonglong2 h2 = *(const ulonglong2*)
                    (s_h + ((2 * ng + b) * 9 + M0 + m) * 128 + k);
                acc[0][b][m] = f2fma(h2.x, wp00, acc[0][b][m]);
                acc[0][b][m] = f2fma(h2.y, wp01, acc[0][b][m]);
                acc[1][b][m] = f2fma(h2.x, wp10, acc[1][b][m]);
                acc[1][b][m] = f2fma(h2.y, wp11, acc[1][b][m]);
            }
        }
    }
    #pragma unroll
    for (int pc = 0; pc < 2; pc++)
        #pragma unroll
        for (int b = 0; b < 2; b++)
            #pragma unroll
            for (int m = 0; m < ML; m++) {
                float2 v = funpack(acc[pc][b][m]);
                s_hc[((2 * ng + b) * 9 + M0 + m) * 256 + p0 + 128 * pc] = v.x + v.y;
            }
}

// ---------------- linear_out: tp[9][2K] @ Wout[2K][K] + skip ----------------
// f32x2 over output-col pairs; tp read as float4 (broadcast), weights LDG.64.
template<int ML, int M0>
__device__ __forceinline__ void lin_out(const float* __restrict__ W,
                                        const float* __restrict__ s_hc,
                                        float* __restrict__ s_res,
                                        int cp, int bg)
{
    u64 acc[ML];
    #pragma unroll
    for (int m = 0; m < ML; m++) acc[m] = 0ull;

    const float* wcol = W + 2 * cp;
    #pragma unroll 2
    for (int p = 0; p < PC; p += 4) {
        u64 w0 = *(const u64*)(wcol + (size_t)(p + 0) * KC);
        u64 w1 = *(const u64*)(wcol + (size_t)(p + 1) * KC);
        u64 w2 = *(const u64*)(wcol + (size_t)(p + 2) * KC);
        u64 w3 = *(const u64*)(wcol + (size_t)(p + 3) * KC);
        #pragma unroll
        for (int m = 0; m < ML; m++) {
            const float4 hv = *(const float4*)
                (s_hc + (bg * 9 + M0 + m) * 256 + p);
            acc[m] = f2fma(fpack(hv.x, hv.x), w0, acc[m]);
            acc[m] = f2fma(fpack(hv.y, hv.y), w1, acc[m]);
            acc[m] = f2fma(fpack(hv.z, hv.z), w2, acc[m]);
            acc[m] = f2fma(fpack(hv.w, hv.w), w3, acc[m]);
        }
    }
    #pragma unroll
    for (int m = 0; m < ML; m++) {
        float* rr = s_res + (bg * 9 + M0 + m) * 128 + 2 * cp;
        float2 r = *(float2*)rr;
        float2 a = funpack(acc[m]);
        r.x += a.x; r.y += a.y;
        *(float2*)rr = r;
    }
}

// ---------------- fused 4-iteration kernel, 8 nodes per CTA, 512 threads ----------------
__global__ void __launch_bounds__(NT, 1)
cg_kernel(const float* __restrict__ f0, const float* __restrict__ f1,
          const float* __restrict__ f2, const float* __restrict__ U,
          const float* __restrict__ gamma, const float* __restrict__ Win,
          const float* __restrict__ Wout, float* __restrict__ out)
{
    extern __shared__ float sm[];
    float* s_res = sm + OFF_RES;
    float* s_h   = sm + OFF_H;
    float* s_hc  = sm + OFF_HC;
    float* s_U   = sm + OFF_U;
    float* s_g   = sm + OFF_G;

    const int tid = threadIdx.x;
    const int n0  = blockIdx.x * BN;

    // --- load features: s_res[b][m][k], m packed [f0 | f1(3) | f2(5)] ---
    {
        float4* dst = (float4*)s_res;
        for (int idx = tid; idx < BN * 9 * 32; idx += NT) {
            int b   = idx / 288;
            int rem = idx - b * 288;
            int m   = rem >> 5;
            int q   = rem & 31;
            int n   = n0 + b;
            const float* src;
            if (m == 0)      src = f0 + (size_t)n * 128;
            else if (m < 4)  src = f1 + (size_t)n * 384 + (m - 1) * 128;
            else             src = f2 + (size_t)n * 640 + (m - 4) * 128;
            dst[idx] = ((const float4*)src)[q];
        }
    }
    // --- symmetrize U into scalar pair layout s_U[pair][c] ---
    for (int tt = tid; tt < 45 * 9; tt += NT) {
        int pair = tt / 9, c = tt - pair * 9;
        int a = 0, rem = pair;
        while (rem > 8 - a) { rem -= 9 - a; a++; }
        int bb = a + rem;
        float u = U[(a * 9 + bb) * 9 + c];
        if (a != bb) u += U[(bb * 9 + a) * 9 + c];
        s_U[pair * 9 + c] = u;
    }
    for (int tt = tid; tt < NI * 3 * KC; tt += NT) s_g[tt] = gamma[tt];
    __syncthreads();

    #pragma unroll 1
    for (int it = 0; it < NI; it++) {
        // ---------- EquivariantRMSNorm -> natural h[b][m][k] ----------
        for (int idx = tid; idx < BN * KC; idx += NT) {
            int b = idx >> 7, k = idx & 127;
            const float* r = s_res + b * 1152 + k;
            float x0 = r[0];
            float x1 = r[128], x2 = r[256],  x3 = r[384];
            float x4 = r[512], x5 = r[640],  x6 = r[768], x7 = r[896], x8 = r[1024];
            float i0 = rsqrtf(x0 * x0 + EPSV);
            float i1 = rsqrtf((x1*x1 + x2*x2 + x3*x3) * (1.0f/3.0f) + EPSV);
            float i2 = rsqrtf((x4*x4 + x5*x5 + x6*x6 + x7*x7 + x8*x8) * 0.2f + EPSV);
            float g0 = s_g[(it * 3 + 0) * 128 + k];
            float g1 = s_g[(it * 3 + 1) * 128 + k];
            float g2 = s_g[(it * 3 + 2) * 128 + k];
            float* h = s_h + b * 1152 + k;
            h[0]    = x0 * i0 * g0;
            h[128]  = x1 * i1 * g1;
            h[256]  = x2 * i1 * g1;
            h[384]  = x3 * i1 * g1;
            h[512]  = x4 * i2 * g2;
            h[640]  = x5 * i2 * g2;
            h[768]  = x6 * i2 * g2;
            h[896]  = x7 * i2 * g2;
            h[1024] = x8 * i2 * g2;
        }
        __syncthreads();

        // ---------- linear_in (K -> 2K), k-parity f32x2 ----------
        {
            const int p0 = tid & 127;
            const int ng = tid >> 7;
            const float* Wi = Win + (size_t)(it * 3) * KC * PC;
            lin_in<1, 0>(Wi + 0 * KC * PC, s_h, s_hc, p0, ng);
            lin_in<3, 1>(Wi + 1 * KC * PC, s_h, s_hc, p0, ng);
            lin_in<5, 4>(Wi + 2 * KC * PC, s_h, s_hc, p0, ng);
        }
        __syncthreads();

        // ---------- CG tensor product, in-place on s_hc, scalar U + fpack ----------
        {
            const int p2 = tid & 127;
            const int bq = (tid >> 7) * 2;
            float* base0 = s_hc + bq * 2304 + 2 * p2;
            float* base1 = base0 + 2304;
            u64 acc0[9], acc1[9];
            #pragma unroll
            for (int c = 0; c < 9; c++) { acc0[c] = 0ull; acc1[c] = 0ull; }
            int pair = 0;
            for (int a = 0; a < 9; a++) {
                u64 va0 = *(const u64*)(base0 + a * 256);
                u64 va1 = *(const u64*)(base1 + a * 256);
                for (int bb = a; bb < 9; bb++) {
                    u64 vb0 = *(const u64*)(base0 + bb * 256);
                    u64 vb1 = *(const u64*)(base1 + bb * 256);
                    u64 pr0 = f2mul(va0, vb0);
                    u64 pr1 = f2mul(va1, vb1);
                    const float* u = s_U + pair * 9;
                    #pragma unroll
                    for (int c = 0; c < 9; c++) {
                        float us = u[c];
                        u64 uc = fpack(us, us);
                        acc0[c] = f2fma(pr0, uc, acc0[c]);
                        acc1[c] = f2fma(pr1, uc, acc1[c]);
                    }
                    pair++;
                }
            }
            #pragma unroll
            for (int c = 0; c < 9; c++) {
                *(u64*)(base0 + c * 256) = acc0[c];
                *(u64*)(base1 + c * 256) = acc1[c];
            }
        }
        __syncthreads();

        // ---------- linear_out (2K -> K) + skip ----------
        {
            const int cp = tid & 63;
            const int bg = tid >> 6;
            const float* Wo = Wout + (size_t)(it * 3) * PC * KC;
            lin_out<1, 0>(Wo + 0 * PC * KC, s_hc, s_res, cp, bg);
            lin_out<3, 1>(Wo + 1 * PC * KC, s_hc, s_res, cp, bg);
            lin_out<5, 4>(Wo + 2 * PC * KC, s_hc, s_res, cp, bg);
        }
        __syncthreads();
    }

    // --- write out [N][9][128] ---
    {
        float4* o = (float4*)(out + (size_t)n0 * 1152);
        const float4* s = (const float4*)s_res;
        for (int idx = tid; idx < BN * 9 * 32; idx += NT) o[idx] = s[idx];
    }
}

extern "C" void kernel_launch(void* const* d_in, const int* in_sizes, int n_in,
                              void* d_out, int out_size)
{
    const float* f0 = (const float*)d_in[0];
    const float* f1 = (const float*)d_in[1];
    const float* f2 = (const float*)d_in[2];
    const float* U  = (const float*)d_in[3];
    const float* g  = (const float*)d_in[4];
    const float* Wi = (const float*)d_in[5];
    const float* Wo = (const float*)d_in[6];
    float* out = (float*)d_out;

    const int smem_bytes = SMEM_FLOATS * (int)sizeof(float);
    cudaFuncSetAttribute(cg_kernel, cudaFuncAttributeMaxDynamicSharedMemorySize, smem_bytes);
    cg_kernel<<<NN / BN, NT, smem_bytes>>>(f0, f1, f2, U, g, Wi, Wo, out);
}